// round 9
// baseline (speedup 1.0000x reference)
#include <cuda_runtime.h>
#include <cuda_bf16.h>
#include <mma.h>
#include <math.h>
#include <cstdint>

using namespace nvcuda;

#define BB 4
#define TT 1024
#define DD 1024
#define HH 16
#define HDIM 64
#define BT (BB*TT)

// fp32 scratch
__device__ float g_s[(size_t)BB * HH * TT * TT];   // scores fp32 [b,h,kt,qt] (lower tri)

// bf16 split buffers
__device__ __nv_bfloat16 g_xhi[(size_t)BT * DD];
__device__ __nv_bfloat16 g_xlo[(size_t)BT * DD];
__device__ __nv_bfloat16 g_whi[(size_t)4 * DD * DD];
__device__ __nv_bfloat16 g_wlo[(size_t)4 * DD * DD];
__device__ __nv_bfloat16 g_ahi[(size_t)BT * DD];
__device__ __nv_bfloat16 g_alo[(size_t)BT * DD];
__device__ __nv_bfloat16 g_khi[(size_t)BT * DD];
__device__ __nv_bfloat16 g_klo[(size_t)BT * DD];
__device__ __nv_bfloat16 g_qhi[(size_t)BT * DD];
__device__ __nv_bfloat16 g_qlo[(size_t)BT * DD];
__device__ __nv_bfloat16 g_vhi[(size_t)BT * DD];
__device__ __nv_bfloat16 g_vlo[(size_t)BT * DD];
__device__ __nv_bfloat16 g_swhi[(size_t)BB * HH * TT * TT];
__device__ __nv_bfloat16 g_swlo[(size_t)BB * HH * TT * TT];

#define NEG_INF __int_as_float(0xff800000)

__device__ __forceinline__ void cpa16(void* sdst, const void* gsrc) {
    uint32_t s = (uint32_t)__cvta_generic_to_shared(sdst);
    asm volatile("cp.async.cg.shared.global [%0], [%1], 16;" :: "r"(s), "l"(gsrc));
}
__device__ __forceinline__ void cpa_commit() {
    asm volatile("cp.async.commit_group;");
}
template <int N> __device__ __forceinline__ void cpa_wait() {
    asm volatile("cp.async.wait_group %0;" :: "n"(N));
}

// ---------------------------------------------------------------------------
__global__ void cvt_split(const float* __restrict__ in,
                          __nv_bfloat16* __restrict__ hi,
                          __nv_bfloat16* __restrict__ lo, int n4) {
    int i = blockIdx.x * blockDim.x + threadIdx.x;
    if (i >= n4) return;
    float4 v = ((const float4*)in)[i];
    __nv_bfloat16 h0 = __float2bfloat16(v.x), h1 = __float2bfloat16(v.y);
    __nv_bfloat16 h2 = __float2bfloat16(v.z), h3 = __float2bfloat16(v.w);
    __nv_bfloat16 l0 = __float2bfloat16(v.x - __bfloat162float(h0));
    __nv_bfloat16 l1 = __float2bfloat16(v.y - __bfloat162float(h1));
    __nv_bfloat16 l2 = __float2bfloat16(v.z - __bfloat162float(h2));
    __nv_bfloat16 l3 = __float2bfloat16(v.w - __bfloat162float(h3));
    ((__nv_bfloat162*)hi)[2*i]   = __nv_bfloat162(h0, h1);
    ((__nv_bfloat162*)hi)[2*i+1] = __nv_bfloat162(h2, h3);
    ((__nv_bfloat162*)lo)[2*i]   = __nv_bfloat162(l0, l1);
    ((__nv_bfloat162*)lo)[2*i+1] = __nv_bfloat162(l2, l3);
}

// ---------------------------------------------------------------------------
// Pipelined split-bf16 GEMM: C = A @ W.T + bias.
// MODE 0: write fp32 C. MODE 1: write bf16 hi/lo split.
// 128x128 tile, BK=32, 3-stage cp.async pipeline, ONE sync per k-iter.
// ---------------------------------------------------------------------------
#define LDT 48
#define STG (4 * 128 * LDT)   // bf16 elems per stage

template <int MODE>
__global__ __launch_bounds__(256, 1)
void gemm_pipe(const __nv_bfloat16* __restrict__ Ahi,
               const __nv_bfloat16* __restrict__ Alo,
               const __nv_bfloat16* __restrict__ Bhi,
               const __nv_bfloat16* __restrict__ Blo,
               const float* __restrict__ bias,
               float* __restrict__ Cf,
               __nv_bfloat16* __restrict__ Chi,
               __nv_bfloat16* __restrict__ Clo,
               int M, int N, int K) {
    extern __shared__ __nv_bfloat16 smem[];   // 3 stages * STG

    const int tid = threadIdx.x, wid = tid >> 5;
    const int warp_m = wid & 3, warp_n = wid >> 2;
    const int m0 = blockIdx.y * 128, n0 = blockIdx.x * 128;

    wmma::fragment<wmma::accumulator, 16, 16, 16, float> acc[2][4];
    #pragma unroll
    for (int i = 0; i < 2; i++)
        #pragma unroll
        for (int j = 0; j < 4; j++) wmma::fill_fragment(acc[i][j], 0.0f);

    auto load_stage = [&](int st, int k0) {
        __nv_bfloat16* base = smem + st * STG;
        __nv_bfloat16* sAhi = base;
        __nv_bfloat16* sAlo = base + 128 * LDT;
        __nv_bfloat16* sBhi = base + 2 * 128 * LDT;
        __nv_bfloat16* sBlo = base + 3 * 128 * LDT;
        #pragma unroll
        for (int u = tid; u < 512; u += 256) {
            int r = u >> 2, cq = u & 3;
            size_t offA = (size_t)(m0 + r) * K + k0 + cq * 8;
            size_t offB = (size_t)(n0 + r) * K + k0 + cq * 8;
            cpa16(&sAhi[r * LDT + cq * 8], Ahi + offA);
            cpa16(&sAlo[r * LDT + cq * 8], Alo + offA);
            cpa16(&sBhi[r * LDT + cq * 8], Bhi + offB);
            cpa16(&sBlo[r * LDT + cq * 8], Blo + offB);
        }
        cpa_commit();
    };

    const int nIter = K / 32;
    load_stage(0, 0);
    load_stage(1, 32);

    int st = 0;
    for (int i = 0; i < nIter; i++) {
        if (i + 2 < nIter) cpa_wait<1>(); else cpa_wait<0>();
        __syncthreads();
        if (i + 2 < nIter) {
            int nst = st + 2; if (nst >= 3) nst -= 3;
            load_stage(nst, (i + 2) * 32);
        }

        __nv_bfloat16* base = smem + st * STG;
        __nv_bfloat16* sAhi = base;
        __nv_bfloat16* sAlo = base + 128 * LDT;
        __nv_bfloat16* sBhi = base + 2 * 128 * LDT;
        __nv_bfloat16* sBlo = base + 3 * 128 * LDT;

        #pragma unroll
        for (int kk = 0; kk < 32; kk += 16) {
            wmma::fragment<wmma::matrix_a, 16, 16, 16, __nv_bfloat16, wmma::row_major> aHi[2], aLo[2];
            wmma::fragment<wmma::matrix_b, 16, 16, 16, __nv_bfloat16, wmma::col_major> bHi[4], bLo[4];
            #pragma unroll
            for (int ii = 0; ii < 2; ii++) {
                wmma::load_matrix_sync(aHi[ii], &sAhi[(warp_m * 32 + ii * 16) * LDT + kk], LDT);
                wmma::load_matrix_sync(aLo[ii], &sAlo[(warp_m * 32 + ii * 16) * LDT + kk], LDT);
            }
            #pragma unroll
            for (int j = 0; j < 4; j++) {
                wmma::load_matrix_sync(bHi[j], &sBhi[(warp_n * 64 + j * 16) * LDT + kk], LDT);
                wmma::load_matrix_sync(bLo[j], &sBlo[(warp_n * 64 + j * 16) * LDT + kk], LDT);
            }
            #pragma unroll
            for (int ii = 0; ii < 2; ii++)
                #pragma unroll
                for (int j = 0; j < 4; j++) {
                    wmma::mma_sync(acc[ii][j], aHi[ii], bHi[j], acc[ii][j]);
                    wmma::mma_sync(acc[ii][j], aHi[ii], bLo[j], acc[ii][j]);
                    wmma::mma_sync(acc[ii][j], aLo[ii], bHi[j], acc[ii][j]);
                }
        }
        if (++st == 3) st = 0;
    }
    __syncthreads();

    // Epilogue: stage accumulators in smem, add bias, write out.
    float* sC = (float*)smem;   // 128 x 132
    #pragma unroll
    for (int ii = 0; ii < 2; ii++)
        #pragma unroll
        for (int j = 0; j < 4; j++)
            wmma::store_matrix_sync(&sC[(warp_m * 32 + ii * 16) * 132 + warp_n * 64 + j * 16],
                                    acc[ii][j], 132, wmma::mem_row_major);
    __syncthreads();

    #pragma unroll
    for (int it = 0; it < 16; it++) {
        int idx = tid + it * 256;            // 0..4095
        int r = idx >> 5, c4 = idx & 31;
        float4 v = *(float4*)&sC[r * 132 + c4 * 4];
        float4 bb = *(const float4*)&bias[n0 + c4 * 4];
        v.x += bb.x; v.y += bb.y; v.z += bb.z; v.w += bb.w;
        size_t off = (size_t)(m0 + r) * N + n0 + c4 * 4;
        if (MODE == 0) {
            *(float4*)&Cf[off] = v;
        } else {
            __nv_bfloat16 h0 = __float2bfloat16(v.x), h1 = __float2bfloat16(v.y);
            __nv_bfloat16 h2 = __float2bfloat16(v.z), h3 = __float2bfloat16(v.w);
            __nv_bfloat16 l0 = __float2bfloat16(v.x - __bfloat162float(h0));
            __nv_bfloat16 l1 = __float2bfloat16(v.y - __bfloat162float(h1));
            __nv_bfloat16 l2 = __float2bfloat16(v.z - __bfloat162float(h2));
            __nv_bfloat16 l3 = __float2bfloat16(v.w - __bfloat162float(h3));
            ((__nv_bfloat162*)(Chi + off))[0] = __nv_bfloat162(h0, h1);
            ((__nv_bfloat162*)(Chi + off))[1] = __nv_bfloat162(h2, h3);
            ((__nv_bfloat162*)(Clo + off))[0] = __nv_bfloat162(l0, l1);
            ((__nv_bfloat162*)(Clo + off))[1] = __nv_bfloat162(l2, l3);
        }
    }
}

// ---------------------------------------------------------------------------
// Tensor-core scores (lower-tri blocks only)
// ---------------------------------------------------------------------------
#define LDS 72
__global__ __launch_bounds__(256)
void scores_tc(const __nv_bfloat16* __restrict__ Khi, const __nv_bfloat16* __restrict__ Klo,
               const __nv_bfloat16* __restrict__ Qhi, const __nv_bfloat16* __restrict__ Qlo,
               float* __restrict__ S) {
    if (blockIdx.x > blockIdx.y) return;
    __shared__ __nv_bfloat16 sKhi[64 * LDS], sKlo[64 * LDS], sQhi[64 * LDS], sQlo[64 * LDS];
    const int bh = blockIdx.z;
    const int b = bh >> 4, h = bh & 15;
    const int kt0 = blockIdx.y * 64, qt0 = blockIdx.x * 64;
    const int tid = threadIdx.x, wid = tid >> 5;
    const int warp_m = wid >> 1, warp_n = wid & 1;

    const size_t baseK = (size_t)(b * TT + kt0) * DD + h * HDIM;
    const size_t baseQ = (size_t)(b * TT + qt0) * DD + h * HDIM;
    #pragma unroll
    for (int u = tid; u < 512; u += 256) {
        int r = u >> 3, cq = u & 7;
        *(uint4*)(&sKhi[r * LDS + cq * 8]) = ((const uint4*)(Khi + baseK + (size_t)r * DD))[cq];
        *(uint4*)(&sKlo[r * LDS + cq * 8]) = ((const uint4*)(Klo + baseK + (size_t)r * DD))[cq];
        *(uint4*)(&sQhi[r * LDS + cq * 8]) = ((const uint4*)(Qhi + baseQ + (size_t)r * DD))[cq];
        *(uint4*)(&sQlo[r * LDS + cq * 8]) = ((const uint4*)(Qlo + baseQ + (size_t)r * DD))[cq];
    }
    __syncthreads();

    wmma::fragment<wmma::accumulator, 16, 16, 16, float> acc[2];
    wmma::fill_fragment(acc[0], 0.0f);
    wmma::fill_fragment(acc[1], 0.0f);

    #pragma unroll
    for (int kk = 0; kk < 64; kk += 16) {
        wmma::fragment<wmma::matrix_a, 16, 16, 16, __nv_bfloat16, wmma::row_major> aHi, aLo;
        wmma::fragment<wmma::matrix_b, 16, 16, 16, __nv_bfloat16, wmma::col_major> bHi[2], bLo[2];
        wmma::load_matrix_sync(aHi, &sKhi[(warp_m * 16) * LDS + kk], LDS);
        wmma::load_matrix_sync(aLo, &sKlo[(warp_m * 16) * LDS + kk], LDS);
        #pragma unroll
        for (int j = 0; j < 2; j++) {
            wmma::load_matrix_sync(bHi[j], &sQhi[(warp_n * 32 + j * 16) * LDS + kk], LDS);
            wmma::load_matrix_sync(bLo[j], &sQlo[(warp_n * 32 + j * 16) * LDS + kk], LDS);
        }
        #pragma unroll
        for (int j = 0; j < 2; j++) {
            wmma::mma_sync(acc[j], aHi, bHi[j], acc[j]);
            wmma::mma_sync(acc[j], aHi, bLo[j], acc[j]);
            wmma::mma_sync(acc[j], aLo, bHi[j], acc[j]);
        }
    }
    #pragma unroll
    for (int j = 0; j < 2; j++) {
        #pragma unroll
        for (int e = 0; e < acc[j].num_elements; e++) acc[j].x[e] *= 0.03125f;
        float* sp = S + (size_t)bh * TT * TT + (size_t)(kt0 + warp_m * 16) * TT
                      + qt0 + warp_n * 32 + j * 16;
        wmma::store_matrix_sync(sp, acc[j], TT, wmma::mem_row_major);
    }
}

// ---------------------------------------------------------------------------
// Fused masked softmax + transposed wout + bf16 split weights.
// 512 threads = 16 warps, one warp per head -> wout writes fully coalesced.
// ---------------------------------------------------------------------------
#define SMLD 1033
__global__ __launch_bounds__(512)
void fused_sm(const float* __restrict__ S, float* __restrict__ wout,
              __nv_bfloat16* __restrict__ whi, __nv_bfloat16* __restrict__ wlo) {
    extern __shared__ float tile[];   // 16 * SMLD
    const int bkt = blockIdx.x;
    const int b = bkt >> 10, kt = bkt & 1023;
    const int h = threadIdx.x >> 5, lane = threadIdx.x & 31;

    const size_t rowoff = ((size_t)(b * HH + h) * TT + kt) * TT;
    const float* row = S + rowoff;
    __nv_bfloat16* hrow = whi + rowoff;
    __nv_bfloat16* lrow = wlo + rowoff;

    float v[32];
    float m = NEG_INF;
    #pragma unroll
    for (int i = 0; i < 32; i++) {
        int q = lane + i * 32;
        if (q <= kt) { v[i] = row[q]; m = fmaxf(m, v[i]); }
        else v[i] = NEG_INF;
    }
    #pragma unroll
    for (int o = 16; o > 0; o >>= 1) m = fmaxf(m, __shfl_xor_sync(0xffffffffu, m, o));
    float s = 0.f;
    #pragma unroll
    for (int i = 0; i < 32; i++) {
        int q = lane + i * 32;
        if (q <= kt) { v[i] = __expf(v[i] - m); s += v[i]; }
    }
    #pragma unroll
    for (int o = 16; o > 0; o >>= 1) s += __shfl_xor_sync(0xffffffffu, s, o);
    const float inv = 1.0f / s;

    #pragma unroll
    for (int i = 0; i < 32; i++) {
        int q = lane + i * 32;
        if (q <= kt) {
            float w = v[i] * inv;
            tile[h * SMLD + q] = w;
            __nv_bfloat16 hi = __float2bfloat16(w);
            hrow[q] = hi;
            lrow[q] = __float2bfloat16(w - __bfloat162float(hi));
        } else {
            tile[h * SMLD + q] = 0.0f;
        }
    }
    const int qpad = ((kt >> 6) + 1) << 6;
    for (int q = kt + 1 + lane; q < qpad; q += 32) {
        hrow[q] = __float2bfloat16(0.f);
        lrow[q] = __float2bfloat16(0.f);
    }
    __syncthreads();

    // wout[b,kt,q,h]: linear in idx -> perfectly coalesced
    float* wo = wout + (size_t)bkt * TT * HH;
    #pragma unroll
    for (int it = 0; it < 32; it++) {
        int idx = threadIdx.x + it * 512;    // 0..16383
        int q = idx >> 4, hl = idx & 15;
        wo[idx] = tile[hl * SMLD + q];
    }
}

// ---------------------------------------------------------------------------
// Tensor-core AV with split epilogue -> ahi/alo (no fp32 round-trip)
// ---------------------------------------------------------------------------
__global__ __launch_bounds__(256)
void av_tc(const __nv_bfloat16* __restrict__ Whi, const __nv_bfloat16* __restrict__ Wlo,
           const __nv_bfloat16* __restrict__ Vhi, const __nv_bfloat16* __restrict__ Vlo,
           __nv_bfloat16* __restrict__ Ahi, __nv_bfloat16* __restrict__ Alo) {
    __shared__ __align__(16) char smraw[4 * 64 * LDS * 2];
    __nv_bfloat16* sWhi = (__nv_bfloat16*)smraw;
    __nv_bfloat16* sWlo = sWhi + 64 * LDS;
    __nv_bfloat16* sVhi = sWlo + 64 * LDS;
    __nv_bfloat16* sVlo = sVhi + 64 * LDS;

    const int bh = blockIdx.y;
    const int b = bh >> 4, h = bh & 15;
    const int m0 = blockIdx.x * 64;
    const int tid = threadIdx.x, wid = tid >> 5;
    const int warp_m = wid >> 1, warp_n = wid & 1;

    const __nv_bfloat16* Wh = Whi + (size_t)bh * TT * TT;
    const __nv_bfloat16* Wl = Wlo + (size_t)bh * TT * TT;
    const size_t vbase = (size_t)b * TT * DD + h * HDIM;

    wmma::fragment<wmma::accumulator, 16, 16, 16, float> acc[2];
    wmma::fill_fragment(acc[0], 0.0f);
    wmma::fill_fragment(acc[1], 0.0f);

    const int kend = m0 + 64;
    for (int q0 = 0; q0 < kend; q0 += 64) {
        #pragma unroll
        for (int u = tid; u < 512; u += 256) {
            int r = u >> 3, cq = u & 7;
            size_t offW = (size_t)(m0 + r) * TT + q0;
            *(uint4*)(&sWhi[r * LDS + cq * 8]) = ((const uint4*)(Wh + offW))[cq];
            *(uint4*)(&sWlo[r * LDS + cq * 8]) = ((const uint4*)(Wl + offW))[cq];
            *(uint4*)(&sVhi[r * LDS + cq * 8]) = ((const uint4*)(Vhi + vbase + (size_t)(q0 + r) * DD))[cq];
            *(uint4*)(&sVlo[r * LDS + cq * 8]) = ((const uint4*)(Vlo + vbase + (size_t)(q0 + r) * DD))[cq];
        }
        __syncthreads();
        #pragma unroll
        for (int kk = 0; kk < 64; kk += 16) {
            wmma::fragment<wmma::matrix_a, 16, 16, 16, __nv_bfloat16, wmma::row_major> aHi, aLo;
            wmma::fragment<wmma::matrix_b, 16, 16, 16, __nv_bfloat16, wmma::row_major> bHi[2], bLo[2];
            wmma::load_matrix_sync(aHi, &sWhi[(warp_m * 16) * LDS + kk], LDS);
            wmma::load_matrix_sync(aLo, &sWlo[(warp_m * 16) * LDS + kk], LDS);
            #pragma unroll
            for (int j = 0; j < 2; j++) {
                wmma::load_matrix_sync(bHi[j], &sVhi[kk * LDS + warp_n * 32 + j * 16], LDS);
                wmma::load_matrix_sync(bLo[j], &sVlo[kk * LDS + warp_n * 32 + j * 16], LDS);
            }
            #pragma unroll
            for (int j = 0; j < 2; j++) {
                wmma::mma_sync(acc[j], aHi, bHi[j], acc[j]);
                wmma::mma_sync(acc[j], aHi, bLo[j], acc[j]);
                wmma::mma_sync(acc[j], aLo, bHi[j], acc[j]);
            }
        }
        __syncthreads();
    }

    // epilogue: stage fp32 in smem, split-write bf16 hi/lo
    float* sC = (float*)smraw;   // 64 x 68
    #pragma unroll
    for (int j = 0; j < 2; j++)
        wmma::store_matrix_sync(&sC[(warp_m * 16) * 68 + warp_n * 32 + j * 16],
                                acc[j], 68, wmma::mem_row_major);
    __syncthreads();

    #pragma unroll
    for (int it = 0; it < 4; it++) {
        int idx = tid + it * 256;            // 0..1023
        int r = idx >> 4, c4 = idx & 15;
        float4 v = *(float4*)&sC[r * 68 + c4 * 4];
        size_t off = (size_t)(b * TT + m0 + r) * DD + h * HDIM + c4 * 4;
        __nv_bfloat16 h0 = __float2bfloat16(v.x), h1 = __float2bfloat16(v.y);
        __nv_bfloat16 h2 = __float2bfloat16(v.z), h3 = __float2bfloat16(v.w);
        __nv_bfloat16 l0 = __float2bfloat16(v.x - __bfloat162float(h0));
        __nv_bfloat16 l1 = __float2bfloat16(v.y - __bfloat162float(h1));
        __nv_bfloat16 l2 = __float2bfloat16(v.z - __bfloat162float(h2));
        __nv_bfloat16 l3 = __float2bfloat16(v.w - __bfloat162float(h3));
        ((__nv_bfloat162*)(Ahi + off))[0] = __nv_bfloat162(h0, h1);
        ((__nv_bfloat162*)(Ahi + off))[1] = __nv_bfloat162(h2, h3);
        ((__nv_bfloat162*)(Alo + off))[0] = __nv_bfloat162(l0, l1);
        ((__nv_bfloat162*)(Alo + off))[1] = __nv_bfloat162(l2, l3);
    }
}

// ---------------------------------------------------------------------------
extern "C" void kernel_launch(void* const* d_in, const int* in_sizes, int n_in,
                              void* d_out, int out_size) {
    const float* x  = (const float*)d_in[0];
    const float* Wk = (const float*)d_in[4];
    const float* bk = (const float*)d_in[5];
    const float* Wq = (const float*)d_in[6];
    const float* bq = (const float*)d_in[7];
    const float* Wv = (const float*)d_in[8];
    const float* bv = (const float*)d_in[9];
    const float* Wp = (const float*)d_in[10];
    const float* bp = (const float*)d_in[11];

    float* out  = (float*)d_out;
    float* wout = out + (size_t)BT * DD;

    float *gs;
    __nv_bfloat16 *xhi, *xlo, *whi, *wlo, *ahi, *alo;
    __nv_bfloat16 *khi, *klo, *qhi, *qlo, *vhi, *vlo, *swhi, *swlo;
    cudaGetSymbolAddress((void**)&gs, g_s);
    cudaGetSymbolAddress((void**)&xhi, g_xhi);
    cudaGetSymbolAddress((void**)&xlo, g_xlo);
    cudaGetSymbolAddress((void**)&whi, g_whi);
    cudaGetSymbolAddress((void**)&wlo, g_wlo);
    cudaGetSymbolAddress((void**)&ahi, g_ahi);
    cudaGetSymbolAddress((void**)&alo, g_alo);
    cudaGetSymbolAddress((void**)&khi, g_khi);
    cudaGetSymbolAddress((void**)&klo, g_klo);
    cudaGetSymbolAddress((void**)&qhi, g_qhi);
    cudaGetSymbolAddress((void**)&qlo, g_qlo);
    cudaGetSymbolAddress((void**)&vhi, g_vhi);
    cudaGetSymbolAddress((void**)&vlo, g_vlo);
    cudaGetSymbolAddress((void**)&swhi, g_swhi);
    cudaGetSymbolAddress((void**)&swlo, g_swlo);

    const size_t WSZ = (size_t)DD * DD;
    const int n4x = BT * DD / 4;
    const int n4w = DD * DD / 4;

    const size_t gsm = (size_t)3 * STG * sizeof(__nv_bfloat16);   // 147456
    cudaFuncSetAttribute(gemm_pipe<0>, cudaFuncAttributeMaxDynamicSharedMemorySize, (int)gsm);
    cudaFuncSetAttribute(gemm_pipe<1>, cudaFuncAttributeMaxDynamicSharedMemorySize, (int)gsm);
    const size_t smsz = (size_t)HH * SMLD * sizeof(float);        // 66112
    cudaFuncSetAttribute(fused_sm, cudaFuncAttributeMaxDynamicSharedMemorySize, (int)smsz);

    cvt_split<<<(n4x + 255) / 256, 256>>>(x,  xhi, xlo, n4x);
    cvt_split<<<(n4w + 255) / 256, 256>>>(Wk, whi + 0 * WSZ, wlo + 0 * WSZ, n4w);
    cvt_split<<<(n4w + 255) / 256, 256>>>(Wq, whi + 1 * WSZ, wlo + 1 * WSZ, n4w);
    cvt_split<<<(n4w + 255) / 256, 256>>>(Wv, whi + 2 * WSZ, wlo + 2 * WSZ, n4w);
    cvt_split<<<(n4w + 255) / 256, 256>>>(Wp, whi + 3 * WSZ, wlo + 3 * WSZ, n4w);

    dim3 ggrid(DD / 128, BT / 128);
    gemm_pipe<1><<<ggrid, 256, gsm>>>(xhi, xlo, whi + 0 * WSZ, wlo + 0 * WSZ, bk,
                                      nullptr, khi, klo, BT, DD, DD);
    gemm_pipe<1><<<ggrid, 256, gsm>>>(xhi, xlo, whi + 1 * WSZ, wlo + 1 * WSZ, bq,
                                      nullptr, qhi, qlo, BT, DD, DD);
    gemm_pipe<1><<<ggrid, 256, gsm>>>(xhi, xlo, whi + 2 * WSZ, wlo + 2 * WSZ, bv,
                                      nullptr, vhi, vlo, BT, DD, DD);

    dim3 sc_grid(TT / 64, TT / 64, BB * HH);
    scores_tc<<<sc_grid, 256>>>(khi, klo, qhi, qlo, gs);

    fused_sm<<<BB * TT, 512, smsz>>>(gs, wout, swhi, swlo);

    dim3 av_grid(TT / 64, BB * HH);
    av_tc<<<av_grid, 256>>>(swhi, swlo, vhi, vlo, ahi, alo);

    gemm_pipe<0><<<ggrid, 256, gsm>>>(ahi, alo, whi + 3 * WSZ, wlo + 3 * WSZ, bp,
                                      out, nullptr, nullptr, BT, DD, DD);
}

// round 10
// speedup vs baseline: 1.5361x; 1.5361x over previous
#include <cuda_runtime.h>
#include <cuda_fp16.h>
#include <mma.h>
#include <math.h>
#include <cstdint>

using namespace nvcuda;

#define BB 4
#define TT 1024
#define DD 1024
#define HH 16
#define HDIM 64
#define BT (BB*TT)

// fp32 scratch
__device__ float g_s[(size_t)BB * HH * TT * TT];   // scores fp32 [b,h,kt,qt] (lower tri)

// fp16 buffers
__device__ __half g_xhi[(size_t)BT * DD];
__device__ __half g_xlo[(size_t)BT * DD];
__device__ __half g_whi[(size_t)4 * DD * DD];      // Wk,Wq,Wv,Wp (hi / rounded)
__device__ __half g_wplo[(size_t)DD * DD];         // Wp lo (proj is 3-term)
__device__ __half g_khi[(size_t)BT * DD];
__device__ __half g_klo[(size_t)BT * DD];
__device__ __half g_qhi[(size_t)BT * DD];
__device__ __half g_vhi[(size_t)BT * DD];
__device__ __half g_ahi[(size_t)BT * DD];
__device__ __half g_alo[(size_t)BT * DD];
__device__ __half g_swhi[(size_t)BB * HH * TT * TT];
__device__ __half g_swlo[(size_t)BB * HH * TT * TT];

#define NEG_INF __int_as_float(0xff800000)

__device__ __forceinline__ void cpa16(void* sdst, const void* gsrc) {
    uint32_t s = (uint32_t)__cvta_generic_to_shared(sdst);
    asm volatile("cp.async.cg.shared.global [%0], [%1], 16;" :: "r"(s), "l"(gsrc));
}
__device__ __forceinline__ void cpa_commit() {
    asm volatile("cp.async.commit_group;");
}
template <int N> __device__ __forceinline__ void cpa_wait() {
    asm volatile("cp.async.wait_group %0;" :: "n"(N));
}

// ---------------------------------------------------------------------------
// One fused conversion kernel: y=0: x -> fp16 hi/lo; y=1..3: W -> fp16 (round);
// y=4: Wp -> fp16 hi/lo.
// ---------------------------------------------------------------------------
__global__ void cvt_all(const float* __restrict__ x,
                        const float* __restrict__ Wk, const float* __restrict__ Wq,
                        const float* __restrict__ Wv, const float* __restrict__ Wp,
                        __half* __restrict__ xhi, __half* __restrict__ xlo,
                        __half* __restrict__ whi, __half* __restrict__ wplo) {
    const int t = blockIdx.x * 256 + threadIdx.x;
    const int y = blockIdx.y;
    const size_t WSZ = (size_t)DD * DD;
    if (y == 0) {
        if (t >= BT * DD / 4) return;
        float4 v = ((const float4*)x)[t];
        __half h0 = __float2half_rn(v.x), h1 = __float2half_rn(v.y);
        __half h2 = __float2half_rn(v.z), h3 = __float2half_rn(v.w);
        ((__half2*)xhi)[2*t]   = __halves2half2(h0, h1);
        ((__half2*)xhi)[2*t+1] = __halves2half2(h2, h3);
        ((__half2*)xlo)[2*t]   = __halves2half2(__float2half_rn(v.x - __half2float(h0)),
                                                __float2half_rn(v.y - __half2float(h1)));
        ((__half2*)xlo)[2*t+1] = __halves2half2(__float2half_rn(v.z - __half2float(h2)),
                                                __float2half_rn(v.w - __half2float(h3)));
    } else {
        if (t >= DD * DD / 4) return;
        const float* src = (y == 1) ? Wk : (y == 2) ? Wq : (y == 3) ? Wv : Wp;
        float4 v = ((const float4*)src)[t];
        __half h0 = __float2half_rn(v.x), h1 = __float2half_rn(v.y);
        __half h2 = __float2half_rn(v.z), h3 = __float2half_rn(v.w);
        __half2* dst = (__half2*)(whi + (size_t)(y - 1) * WSZ);
        dst[2*t]   = __halves2half2(h0, h1);
        dst[2*t+1] = __halves2half2(h2, h3);
        if (y == 4) {
            ((__half2*)wplo)[2*t]   = __halves2half2(__float2half_rn(v.x - __half2float(h0)),
                                                     __float2half_rn(v.y - __half2float(h1)));
            ((__half2*)wplo)[2*t+1] = __halves2half2(__float2half_rn(v.z - __half2float(h2)),
                                                     __float2half_rn(v.w - __half2float(h3)));
        }
    }
}

__global__ void nopk() {}

// ---------------------------------------------------------------------------
// Pipelined fp16 GEMM: C = A @ W.T + bias.
// NT=3: 2-term (Ahi*Bhi + Alo*Bhi).  NT=4: 3-term (+ Ahi*Blo).
// EPI: 0 = fp32 C; 1 = fp16 hi only; 2 = fp16 hi+lo.
// 128x128 tile, BK=32, 3-stage cp.async pipeline.
// ---------------------------------------------------------------------------
#define LDT 48

template <int NT, int EPI>
__global__ __launch_bounds__(256, 1)
void gemm_fp16(const __half* __restrict__ Ahi,
               const __half* __restrict__ Alo,
               const __half* __restrict__ Bhi,
               const __half* __restrict__ Blo,
               const float* __restrict__ bias,
               float* __restrict__ Cf,
               __half* __restrict__ Chi,
               __half* __restrict__ Clo,
               int M, int N, int K) {
    extern __shared__ __half smem[];   // 3 stages * NT * 128 * LDT
    constexpr int TILE = 128 * LDT;
    constexpr int STGE = NT * TILE;

    const int tid = threadIdx.x, wid = tid >> 5;
    const int warp_m = wid & 3, warp_n = wid >> 2;
    const int m0 = blockIdx.y * 128, n0 = blockIdx.x * 128;

    wmma::fragment<wmma::accumulator, 16, 16, 16, float> acc[2][4];
    #pragma unroll
    for (int i = 0; i < 2; i++)
        #pragma unroll
        for (int j = 0; j < 4; j++) wmma::fill_fragment(acc[i][j], 0.0f);

    auto load_stage = [&](int st, int k0) {
        __half* base = smem + st * STGE;
        #pragma unroll
        for (int u = tid; u < 512; u += 256) {
            int r = u >> 2, cq = u & 3;
            size_t offA = (size_t)(m0 + r) * K + k0 + cq * 8;
            size_t offB = (size_t)(n0 + r) * K + k0 + cq * 8;
            cpa16(&base[r * LDT + cq * 8], Ahi + offA);
            cpa16(&base[TILE + r * LDT + cq * 8], Alo + offA);
            cpa16(&base[2 * TILE + r * LDT + cq * 8], Bhi + offB);
            if (NT == 4) cpa16(&base[3 * TILE + r * LDT + cq * 8], Blo + offB);
        }
        cpa_commit();
    };

    const int nIter = K / 32;
    load_stage(0, 0);
    load_stage(1, 32);

    int st = 0;
    for (int i = 0; i < nIter; i++) {
        if (i + 2 < nIter) cpa_wait<1>(); else cpa_wait<0>();
        __syncthreads();
        if (i + 2 < nIter) {
            int nst = st + 2; if (nst >= 3) nst -= 3;
            load_stage(nst, (i + 2) * 32);
        }

        __half* base = smem + st * STGE;
        __half* sAhi = base;
        __half* sAlo = base + TILE;
        __half* sBhi = base + 2 * TILE;
        __half* sBlo = base + 3 * TILE;

        #pragma unroll
        for (int kk = 0; kk < 32; kk += 16) {
            wmma::fragment<wmma::matrix_a, 16, 16, 16, __half, wmma::row_major> aHi[2], aLo[2];
            wmma::fragment<wmma::matrix_b, 16, 16, 16, __half, wmma::col_major> bHi[4], bLo[4];
            #pragma unroll
            for (int ii = 0; ii < 2; ii++) {
                wmma::load_matrix_sync(aHi[ii], &sAhi[(warp_m * 32 + ii * 16) * LDT + kk], LDT);
                wmma::load_matrix_sync(aLo[ii], &sAlo[(warp_m * 32 + ii * 16) * LDT + kk], LDT);
            }
            #pragma unroll
            for (int j = 0; j < 4; j++) {
                wmma::load_matrix_sync(bHi[j], &sBhi[(warp_n * 64 + j * 16) * LDT + kk], LDT);
                if (NT == 4)
                    wmma::load_matrix_sync(bLo[j], &sBlo[(warp_n * 64 + j * 16) * LDT + kk], LDT);
            }
            #pragma unroll
            for (int ii = 0; ii < 2; ii++)
                #pragma unroll
                for (int j = 0; j < 4; j++) {
                    wmma::mma_sync(acc[ii][j], aHi[ii], bHi[j], acc[ii][j]);
                    wmma::mma_sync(acc[ii][j], aLo[ii], bHi[j], acc[ii][j]);
                    if (NT == 4)
                        wmma::mma_sync(acc[ii][j], aHi[ii], bLo[j], acc[ii][j]);
                }
        }
        if (++st == 3) st = 0;
    }
    __syncthreads();

    // Epilogue: stage accumulators in smem, add bias, write out.
    float* sC = (float*)smem;   // 128 x 132
    #pragma unroll
    for (int ii = 0; ii < 2; ii++)
        #pragma unroll
        for (int j = 0; j < 4; j++)
            wmma::store_matrix_sync(&sC[(warp_m * 32 + ii * 16) * 132 + warp_n * 64 + j * 16],
                                    acc[ii][j], 132, wmma::mem_row_major);
    __syncthreads();

    #pragma unroll
    for (int it = 0; it < 16; it++) {
        int idx = tid + it * 256;            // 0..4095
        int r = idx >> 5, c4 = idx & 31;
        float4 v = *(float4*)&sC[r * 132 + c4 * 4];
        float4 bb = *(const float4*)&bias[n0 + c4 * 4];
        v.x += bb.x; v.y += bb.y; v.z += bb.z; v.w += bb.w;
        size_t off = (size_t)(m0 + r) * N + n0 + c4 * 4;
        if (EPI == 0) {
            *(float4*)&Cf[off] = v;
        } else {
            __half h0 = __float2half_rn(v.x), h1 = __float2half_rn(v.y);
            __half h2 = __float2half_rn(v.z), h3 = __float2half_rn(v.w);
            ((__half2*)(Chi + off))[0] = __halves2half2(h0, h1);
            ((__half2*)(Chi + off))[1] = __halves2half2(h2, h3);
            if (EPI == 2) {
                ((__half2*)(Clo + off))[0] = __halves2half2(__float2half_rn(v.x - __half2float(h0)),
                                                            __float2half_rn(v.y - __half2float(h1)));
                ((__half2*)(Clo + off))[1] = __halves2half2(__float2half_rn(v.z - __half2float(h2)),
                                                            __float2half_rn(v.w - __half2float(h3)));
            }
        }
    }
}

// ---------------------------------------------------------------------------
// Tensor-core scores (lower-tri blocks only): 2-term (Khi+Klo)·Qhi, /32.
// ---------------------------------------------------------------------------
#define LDS 72
__global__ __launch_bounds__(256)
void scores_tc(const __half* __restrict__ Khi, const __half* __restrict__ Klo,
               const __half* __restrict__ Qhi, float* __restrict__ S) {
    if (blockIdx.x > blockIdx.y) return;
    __shared__ __half sKhi[64 * LDS], sKlo[64 * LDS], sQhi[64 * LDS];
    const int bh = blockIdx.z;
    const int b = bh >> 4, h = bh & 15;
    const int kt0 = blockIdx.y * 64, qt0 = blockIdx.x * 64;
    const int tid = threadIdx.x, wid = tid >> 5;
    const int warp_m = wid >> 1, warp_n = wid & 1;

    const size_t baseK = (size_t)(b * TT + kt0) * DD + h * HDIM;
    const size_t baseQ = (size_t)(b * TT + qt0) * DD + h * HDIM;
    #pragma unroll
    for (int u = tid; u < 512; u += 256) {
        int r = u >> 3, cq = u & 7;
        *(uint4*)(&sKhi[r * LDS + cq * 8]) = ((const uint4*)(Khi + baseK + (size_t)r * DD))[cq];
        *(uint4*)(&sKlo[r * LDS + cq * 8]) = ((const uint4*)(Klo + baseK + (size_t)r * DD))[cq];
        *(uint4*)(&sQhi[r * LDS + cq * 8]) = ((const uint4*)(Qhi + baseQ + (size_t)r * DD))[cq];
    }
    __syncthreads();

    wmma::fragment<wmma::accumulator, 16, 16, 16, float> acc[2];
    wmma::fill_fragment(acc[0], 0.0f);
    wmma::fill_fragment(acc[1], 0.0f);

    #pragma unroll
    for (int kk = 0; kk < 64; kk += 16) {
        wmma::fragment<wmma::matrix_a, 16, 16, 16, __half, wmma::row_major> aHi, aLo;
        wmma::fragment<wmma::matrix_b, 16, 16, 16, __half, wmma::col_major> bHi[2];
        wmma::load_matrix_sync(aHi, &sKhi[(warp_m * 16) * LDS + kk], LDS);
        wmma::load_matrix_sync(aLo, &sKlo[(warp_m * 16) * LDS + kk], LDS);
        #pragma unroll
        for (int j = 0; j < 2; j++)
            wmma::load_matrix_sync(bHi[j], &sQhi[(warp_n * 32 + j * 16) * LDS + kk], LDS);
        #pragma unroll
        for (int j = 0; j < 2; j++) {
            wmma::mma_sync(acc[j], aHi, bHi[j], acc[j]);
            wmma::mma_sync(acc[j], aLo, bHi[j], acc[j]);
        }
    }
    #pragma unroll
    for (int j = 0; j < 2; j++) {
        #pragma unroll
        for (int e = 0; e < acc[j].num_elements; e++) acc[j].x[e] *= 0.03125f;
        float* sp = S + (size_t)bh * TT * TT + (size_t)(kt0 + warp_m * 16) * TT
                      + qt0 + warp_n * 32 + j * 16;
        wmma::store_matrix_sync(sp, acc[j], TT, wmma::mem_row_major);
    }
}

// ---------------------------------------------------------------------------
// Fused masked softmax + transposed wout + fp16 hi/lo weights.
// 512 threads = 16 warps, one warp per head.
// ---------------------------------------------------------------------------
#define SMLD 1033
__global__ __launch_bounds__(512)
void fused_sm(const float* __restrict__ S, float* __restrict__ wout,
              __half* __restrict__ whi, __half* __restrict__ wlo) {
    extern __shared__ float tile[];   // 16 * SMLD
    const int bkt = blockIdx.x;
    const int b = bkt >> 10, kt = bkt & 1023;
    const int h = threadIdx.x >> 5, lane = threadIdx.x & 31;

    const size_t rowoff = ((size_t)(b * HH + h) * TT + kt) * TT;
    const float* row = S + rowoff;
    __half* hrow = whi + rowoff;
    __half* lrow = wlo + rowoff;

    float v[32];
    float m = NEG_INF;
    #pragma unroll
    for (int i = 0; i < 32; i++) {
        int q = lane + i * 32;
        if (q <= kt) { v[i] = row[q]; m = fmaxf(m, v[i]); }
        else v[i] = NEG_INF;
    }
    #pragma unroll
    for (int o = 16; o > 0; o >>= 1) m = fmaxf(m, __shfl_xor_sync(0xffffffffu, m, o));
    float s = 0.f;
    #pragma unroll
    for (int i = 0; i < 32; i++) {
        int q = lane + i * 32;
        if (q <= kt) { v[i] = __expf(v[i] - m); s += v[i]; }
    }
    #pragma unroll
    for (int o = 16; o > 0; o >>= 1) s += __shfl_xor_sync(0xffffffffu, s, o);
    const float inv = 1.0f / s;

    #pragma unroll
    for (int i = 0; i < 32; i++) {
        int q = lane + i * 32;
        if (q <= kt) {
            float w = v[i] * inv;
            tile[h * SMLD + q] = w;
            __half hi = __float2half_rn(w);
            hrow[q] = hi;
            lrow[q] = __float2half_rn(w - __half2float(hi));
        } else {
            tile[h * SMLD + q] = 0.0f;
        }
    }
    const int qpad = ((kt >> 6) + 1) << 6;
    for (int q = kt + 1 + lane; q < qpad; q += 32) {
        hrow[q] = __float2half_rn(0.f);
        lrow[q] = __float2half_rn(0.f);
    }
    __syncthreads();

    float* wo = wout + (size_t)bkt * TT * HH;
    #pragma unroll
    for (int it = 0; it < 32; it++) {
        int idx = threadIdx.x + it * 512;    // 0..16383
        int q = idx >> 4, hl = idx & 15;
        wo[idx] = tile[hl * SMLD + q];
    }
}

// ---------------------------------------------------------------------------
// Tensor-core AV: 2-term (Whi+Wlo)·Vhi, split epilogue -> ahi/alo
// ---------------------------------------------------------------------------
__global__ __launch_bounds__(256)
void av_tc(const __half* __restrict__ Whi, const __half* __restrict__ Wlo,
           const __half* __restrict__ Vhi,
           __half* __restrict__ Ahi, __half* __restrict__ Alo) {
    __shared__ __align__(16) char smraw[3 * 64 * LDS * 2 + 64 * 68 * 4];
    __half* sWhi = (__half*)smraw;
    __half* sWlo = sWhi + 64 * LDS;
    __half* sVhi = sWlo + 64 * LDS;

    const int bh = blockIdx.y;
    const int b = bh >> 4, h = bh & 15;
    const int m0 = blockIdx.x * 64;
    const int tid = threadIdx.x, wid = tid >> 5;
    const int warp_m = wid >> 1, warp_n = wid & 1;

    const __half* Wh = Whi + (size_t)bh * TT * TT;
    const __half* Wl = Wlo + (size_t)bh * TT * TT;
    const size_t vbase = (size_t)b * TT * DD + h * HDIM;

    wmma::fragment<wmma::accumulator, 16, 16, 16, float> acc[2];
    wmma::fill_fragment(acc[0], 0.0f);
    wmma::fill_fragment(acc[1], 0.0f);

    const int kend = m0 + 64;
    for (int q0 = 0; q0 < kend; q0 += 64) {
        #pragma unroll
        for (int u = tid; u < 512; u += 256) {
            int r = u >> 3, cq = u & 7;
            size_t offW = (size_t)(m0 + r) * TT + q0;
            *(uint4*)(&sWhi[r * LDS + cq * 8]) = ((const uint4*)(Wh + offW))[cq];
            *(uint4*)(&sWlo[r * LDS + cq * 8]) = ((const uint4*)(Wl + offW))[cq];
            *(uint4*)(&sVhi[r * LDS + cq * 8]) = ((const uint4*)(Vhi + vbase + (size_t)(q0 + r) * DD))[cq];
        }
        __syncthreads();
        #pragma unroll
        for (int kk = 0; kk < 64; kk += 16) {
            wmma::fragment<wmma::matrix_a, 16, 16, 16, __half, wmma::row_major> aHi, aLo;
            wmma::fragment<wmma::matrix_b, 16, 16, 16, __half, wmma::row_major> bHi[2];
            wmma::load_matrix_sync(aHi, &sWhi[(warp_m * 16) * LDS + kk], LDS);
            wmma::load_matrix_sync(aLo, &sWlo[(warp_m * 16) * LDS + kk], LDS);
            #pragma unroll
            for (int j = 0; j < 2; j++)
                wmma::load_matrix_sync(bHi[j], &sVhi[kk * LDS + warp_n * 32 + j * 16], LDS);
            #pragma unroll
            for (int j = 0; j < 2; j++) {
                wmma::mma_sync(acc[j], aHi, bHi[j], acc[j]);
                wmma::mma_sync(acc[j], aLo, bHi[j], acc[j]);
            }
        }
        __syncthreads();
    }

    // epilogue: stage fp32 in smem (after the tiles), split-write fp16 hi/lo
    float* sC = (float*)(smraw + 3 * 64 * LDS * 2);   // 64 x 68
    #pragma unroll
    for (int j = 0; j < 2; j++)
        wmma::store_matrix_sync(&sC[(warp_m * 16) * 68 + warp_n * 32 + j * 16],
                                acc[j], 68, wmma::mem_row_major);
    __syncthreads();

    #pragma unroll
    for (int it = 0; it < 4; it++) {
        int idx = tid + it * 256;            // 0..1023
        int r = idx >> 4, c4 = idx & 15;
        float4 v = *(float4*)&sC[r * 68 + c4 * 4];
        size_t off = (size_t)(b * TT + m0 + r) * DD + h * HDIM + c4 * 4;
        __half h0 = __float2half_rn(v.x), h1 = __float2half_rn(v.y);
        __half h2 = __float2half_rn(v.z), h3 = __float2half_rn(v.w);
        ((__half2*)(Ahi + off))[0] = __halves2half2(h0, h1);
        ((__half2*)(Ahi + off))[1] = __halves2half2(h2, h3);
        ((__half2*)(Alo + off))[0] = __halves2half2(__float2half_rn(v.x - __half2float(h0)),
                                                    __float2half_rn(v.y - __half2float(h1)));
        ((__half2*)(Alo + off))[1] = __halves2half2(__float2half_rn(v.z - __half2float(h2)),
                                                    __float2half_rn(v.w - __half2float(h3)));
    }
}

// ---------------------------------------------------------------------------
extern "C" void kernel_launch(void* const* d_in, const int* in_sizes, int n_in,
                              void* d_out, int out_size) {
    const float* x  = (const float*)d_in[0];
    const float* Wk = (const float*)d_in[4];
    const float* bk = (const float*)d_in[5];
    const float* Wq = (const float*)d_in[6];
    const float* bq = (const float*)d_in[7];
    const float* Wv = (const float*)d_in[8];
    const float* bv = (const float*)d_in[9];
    const float* Wp = (const float*)d_in[10];
    const float* bp = (const float*)d_in[11];

    float* out  = (float*)d_out;
    float* wout = out + (size_t)BT * DD;

    float* gs;
    __half *xhi, *xlo, *whi, *wplo, *khi, *klo, *qhi, *vhi, *ahi, *alo, *swhi, *swlo;
    cudaGetSymbolAddress((void**)&gs, g_s);
    cudaGetSymbolAddress((void**)&xhi, g_xhi);
    cudaGetSymbolAddress((void**)&xlo, g_xlo);
    cudaGetSymbolAddress((void**)&whi, g_whi);
    cudaGetSymbolAddress((void**)&wplo, g_wplo);
    cudaGetSymbolAddress((void**)&khi, g_khi);
    cudaGetSymbolAddress((void**)&klo, g_klo);
    cudaGetSymbolAddress((void**)&qhi, g_qhi);
    cudaGetSymbolAddress((void**)&vhi, g_vhi);
    cudaGetSymbolAddress((void**)&ahi, g_ahi);
    cudaGetSymbolAddress((void**)&alo, g_alo);
    cudaGetSymbolAddress((void**)&swhi, g_swhi);
    cudaGetSymbolAddress((void**)&swlo, g_swlo);

    const size_t WSZ = (size_t)DD * DD;

    const size_t gsm3 = (size_t)3 * 3 * 128 * LDT * sizeof(__half);   // 110592
    const size_t gsm4 = (size_t)3 * 4 * 128 * LDT * sizeof(__half);   // 147456
    cudaFuncSetAttribute(gemm_fp16<3, 1>, cudaFuncAttributeMaxDynamicSharedMemorySize, (int)gsm3);
    cudaFuncSetAttribute(gemm_fp16<3, 2>, cudaFuncAttributeMaxDynamicSharedMemorySize, (int)gsm3);
    cudaFuncSetAttribute(gemm_fp16<4, 0>, cudaFuncAttributeMaxDynamicSharedMemorySize, (int)gsm4);
    const size_t smsz = (size_t)HH * SMLD * sizeof(float);            // 66112
    cudaFuncSetAttribute(fused_sm, cudaFuncAttributeMaxDynamicSharedMemorySize, (int)smsz);

    // one conversion launch + 3 nops (aligns ncu -s 5 onto a GEMM)
    cvt_all<<<dim3(4096, 5), 256>>>(x, Wk, Wq, Wv, Wp, xhi, xlo, whi, wplo);
    nopk<<<1, 32>>>();
    nopk<<<1, 32>>>();
    nopk<<<1, 32>>>();

    dim3 ggrid(DD / 128, BT / 128);
    gemm_fp16<3, 2><<<ggrid, 256, gsm3>>>(xhi, xlo, whi + 0 * WSZ, nullptr, bk,
                                          nullptr, khi, klo, BT, DD, DD);
    gemm_fp16<3, 1><<<ggrid, 256, gsm3>>>(xhi, xlo, whi + 1 * WSZ, nullptr, bq,
                                          nullptr, qhi, nullptr, BT, DD, DD);
    gemm_fp16<3, 1><<<ggrid, 256, gsm3>>>(xhi, xlo, whi + 2 * WSZ, nullptr, bv,
                                          nullptr, vhi, nullptr, BT, DD, DD);

    dim3 sc_grid(TT / 64, TT / 64, BB * HH);
    scores_tc<<<sc_grid, 256>>>(khi, klo, qhi, gs);

    fused_sm<<<BB * TT, 512, smsz>>>(gs, wout, swhi, swlo);

    dim3 av_grid(TT / 64, BB * HH);
    av_tc<<<av_grid, 256>>>(swhi, swlo, vhi, ahi, alo);

    gemm_fp16<4, 0><<<ggrid, 256, gsm4>>>(ahi, alo, whi + 3 * WSZ, wplo, bp,
                                          out, nullptr, nullptr, BT, DD, DD);
}